// round 1
// baseline (speedup 1.0000x reference)
#include <cuda_runtime.h>
#include <cstdint>

// VecArrayMultiplier54x54: the reference's differentiable gate network is
// exact on {0,1} inputs, so output[row] = bits of (uint54(A[row]) * uint54(B[row])),
// LSB first, as 0.0/1.0 floats.
//
// One warp per batch row:
//   - lanes cooperatively load the 54 input floats (coalesced),
//   - __ballot_sync packs them into a 54-bit integer,
//   - every lane computes the 128-bit product (cheap, avoids shuffles),
//   - lanes cooperatively write the 108 output bits (coalesced).

__global__ void mul54x54_kernel(const float* __restrict__ A,
                                const float* __restrict__ B,
                                float* __restrict__ out,
                                int batch) {
    const int gwarp = (int)((blockIdx.x * blockDim.x + threadIdx.x) >> 5);
    const int lane  = threadIdx.x & 31;
    if (gwarp >= batch) return;

    const float* __restrict__ a_row = A + (size_t)gwarp * 54;
    const float* __restrict__ b_row = B + (size_t)gwarp * 54;

    // Load bits: lane l covers indices l and 32+l (only lanes 0..21 for the tail).
    float av0 = a_row[lane];
    float bv0 = b_row[lane];
    float av1 = 0.0f, bv1 = 0.0f;
    if (lane < 22) {
        av1 = a_row[32 + lane];
        bv1 = b_row[32 + lane];
    }

    unsigned ma0 = __ballot_sync(0xFFFFFFFFu, av0 > 0.5f);
    unsigned ma1 = __ballot_sync(0xFFFFFFFFu, av1 > 0.5f);
    unsigned mb0 = __ballot_sync(0xFFFFFFFFu, bv0 > 0.5f);
    unsigned mb1 = __ballot_sync(0xFFFFFFFFu, bv1 > 0.5f);

    const uint64_t a = (uint64_t)ma0 | ((uint64_t)(ma1 & 0x3FFFFFu) << 32);
    const uint64_t b = (uint64_t)mb0 | ((uint64_t)(mb1 & 0x3FFFFFu) << 32);

    const uint64_t lo = a * b;               // product bits [0:64)
    const uint64_t hi = __umul64hi(a, b);    // product bits [64:128), only [64:108) nonzero

    float* __restrict__ o = out + (size_t)gwarp * 108;

    // 108 outputs = 3 full lanesweeps + 12-lane tail, all coalesced.
    o[lane]      = (float)((unsigned)(lo >>  lane)        & 1u);
    o[32 + lane] = (float)((unsigned)(lo >> (32 + lane))  & 1u);
    o[64 + lane] = (float)((unsigned)(hi >>  lane)        & 1u);
    if (lane < 12)
        o[96 + lane] = (float)((unsigned)(hi >> (32 + lane)) & 1u);
}

extern "C" void kernel_launch(void* const* d_in, const int* in_sizes, int n_in,
                              void* d_out, int out_size) {
    const float* A = (const float*)d_in[0];
    const float* B = (const float*)d_in[1];
    float* out = (float*)d_out;

    const int batch = in_sizes[0] / 54;          // 8192 expected
    const int threads = 256;                     // 8 warps/block
    const int warpsPerBlock = threads / 32;
    const int blocks = (batch + warpsPerBlock - 1) / warpsPerBlock;

    mul54x54_kernel<<<blocks, threads>>>(A, B, out, batch);
}